// round 3
// baseline (speedup 1.0000x reference)
#include <cuda_runtime.h>
#include <cuda_bf16.h>
#include <cstdint>

// MarginalLoss: out = m * sum_{j>=i} (XI + ind_ij * max(THETA - dist2_ij, 0))
// dist2 = 2 - 2*dot(n_i, n_j) for L2-normalized rows -> hinge = max(2g - 0.8, 0)

#define THETA_F 1.2f
#define XI_D 0.3

#define BM 128
#define BK 64
#define LDS_ (BK + 8)  // bf16 elements per smem row (144B stride: ldmatrix conflict-free)

// scratch: normalized matrix in bf16 (B=8192, D=512 fixed by the problem)
__device__ __align__(16) __nv_bfloat16 g_N[8192 * 512];
__device__ double g_total;
__device__ int g_is64;

// ---------------------------------------------------------------------------
__global__ void zero_kernel() {
    g_total = 0.0;
    g_is64 = 1;
}

// Detect label dtype: if y is int64, the high 32-bit word of each entry is 0
// (labels are in [0,1000)). Reads only the first B 32-bit words, which is
// within the allocation whether y is int32 (B words) or int64 (2B words).
__global__ void detect_kernel(const unsigned* __restrict__ yw, int B) {
    int i = blockIdx.x * blockDim.x + threadIdx.x;
    if (i < B / 2) {
        if (yw[2 * i + 1] != 0u) atomicAnd(&g_is64, 0);
    }
}

// ---------------------------------------------------------------------------
// warp-per-row L2 normalize, fp32 -> bf16
__global__ void normalize_kernel(const float* __restrict__ x, int B, int D) {
    int wid = threadIdx.x >> 5, lane = threadIdx.x & 31;
    int row = blockIdx.x * 8 + wid;
    if (row >= B) return;
    const float4* xr = (const float4*)(x + (size_t)row * D);
    int nf4 = D >> 2;
    float s = 0.f;
    for (int p = lane; p < nf4; p += 32) {
        float4 v = xr[p];
        s += v.x * v.x + v.y * v.y + v.z * v.z + v.w * v.w;
    }
#pragma unroll
    for (int o = 16; o; o >>= 1) s += __shfl_xor_sync(0xffffffffu, s, o);
    float rinv = rsqrtf(s);
    __nv_bfloat162* out = (__nv_bfloat162*)(g_N + (size_t)row * D);
    for (int p = lane; p < nf4; p += 32) {
        float4 v = xr[p];
        out[2 * p]     = __floats2bfloat162_rn(v.x * rinv, v.y * rinv);
        out[2 * p + 1] = __floats2bfloat162_rn(v.z * rinv, v.w * rinv);
    }
}

// ---------------------------------------------------------------------------
__device__ __forceinline__ void ldsm_x4(uint32_t& r0, uint32_t& r1,
                                        uint32_t& r2, uint32_t& r3,
                                        uint32_t addr) {
    asm volatile("ldmatrix.sync.aligned.m8n8.x4.shared.b16 {%0,%1,%2,%3}, [%4];"
                 : "=r"(r0), "=r"(r1), "=r"(r2), "=r"(r3)
                 : "r"(addr));
}

__device__ __forceinline__ void mma16816(float* c, const uint32_t* a, const uint32_t* b) {
    asm volatile(
        "mma.sync.aligned.m16n8k16.row.col.f32.bf16.bf16.f32 "
        "{%0,%1,%2,%3}, {%4,%5,%6,%7}, {%8,%9}, {%0,%1,%2,%3};"
        : "+f"(c[0]), "+f"(c[1]), "+f"(c[2]), "+f"(c[3])
        : "r"(a[0]), "r"(a[1]), "r"(a[2]), "r"(a[3]), "r"(b[0]), "r"(b[1]));
}

// One CTA computes one 128x128 tile of G = N N^T (upper-triangle tiles only)
// and reduces sum of ind * max(2g - 0.8, 0) over the masked region.
__global__ __launch_bounds__(256, 2)
void gemm_kernel(const void* __restrict__ yv, int B, int D, int NT) {
    __shared__ __align__(16) __nv_bfloat16 As[BM * LDS_];
    __shared__ __align__(16) __nv_bfloat16 Bs[BM * LDS_];
    __shared__ int ysi[128], ysj[128];
    __shared__ float wsum[8];

    // decode linear block id -> upper-triangle tile (ti, tj), tj >= ti.
    // reverse-index trick: k enumerates a lower triangle with row sizes 1..NT
    int T = NT * (NT + 1) / 2;
    int kidx = T - 1 - (int)blockIdx.x;
    int p = (int)((sqrtf(8.f * (float)kidx + 1.f) - 1.f) * 0.5f);
    while ((p + 1) * (p + 2) / 2 <= kidx) p++;
    while (p * (p + 1) / 2 > kidx) p--;
    int q = kidx - p * (p + 1) / 2;
    int ti = NT - 1 - p, tj = NT - 1 - q;

    int i0 = ti * 128, j0 = tj * 128;

    int tid = threadIdx.x;
    int lane = tid & 31, wid = tid >> 5;
    int warp_m = wid & 1;   // 2 warp-rows of 64
    int warp_n = wid >> 1;  // 4 warp-cols of 32

    // stage labels (dtype decided at runtime by detect_kernel)
    {
        int is64 = g_is64;
        if (tid < 128) {
            ysi[tid] = is64 ? (int)((const long long*)yv)[i0 + tid]
                            : ((const int*)yv)[i0 + tid];
        } else {
            int t2 = tid - 128;
            ysj[t2] = is64 ? (int)((const long long*)yv)[j0 + t2]
                           : ((const int*)yv)[j0 + t2];
        }
    }

    float acc[4][4][4];
#pragma unroll
    for (int mi = 0; mi < 4; mi++)
#pragma unroll
        for (int ni = 0; ni < 4; ni++)
#pragma unroll
            for (int e = 0; e < 4; e++) acc[mi][ni][e] = 0.f;

    int lrow = tid >> 4;          // 0..15
    int lcol = (tid & 15) * 4;    // 0..60, step 4 elems (8B)
    const __nv_bfloat16* Nb = g_N;

    uint32_t sA = (uint32_t)__cvta_generic_to_shared(As);
    uint32_t sB = (uint32_t)__cvta_generic_to_shared(Bs);
    int arow = lane & 15, ak = 8 * (lane >> 4);
    int brow = (lane & 7) | ((lane >> 1) & 8), bk = 8 * ((lane >> 3) & 1);

    for (int kt = 0; kt < D; kt += BK) {
        __syncthreads();
#pragma unroll
        for (int r = 0; r < 8; r++) {
            int m = lrow + r * 16;
            *(uint2*)&As[m * LDS_ + lcol] =
                *(const uint2*)(Nb + (size_t)(i0 + m) * D + kt + lcol);
            *(uint2*)&Bs[m * LDS_ + lcol] =
                *(const uint2*)(Nb + (size_t)(j0 + m) * D + kt + lcol);
        }
        __syncthreads();

#pragma unroll
        for (int ks = 0; ks < BK / 16; ks++) {
            int k0 = ks * 16;
            uint32_t a[4][4], b[4][2];
#pragma unroll
            for (int mi = 0; mi < 4; mi++) {
                uint32_t addr =
                    sA + 2u * ((uint32_t)((warp_m * 64 + mi * 16 + arow) * LDS_ + k0 + ak));
                ldsm_x4(a[mi][0], a[mi][1], a[mi][2], a[mi][3], addr);
            }
#pragma unroll
            for (int nb = 0; nb < 2; nb++) {
                uint32_t addr =
                    sB + 2u * ((uint32_t)((warp_n * 32 + nb * 16 + brow) * LDS_ + k0 + bk));
                uint32_t r0, r1, r2, r3;
                ldsm_x4(r0, r1, r2, r3, addr);
                b[nb * 2][0] = r0; b[nb * 2][1] = r1;
                b[nb * 2 + 1][0] = r2; b[nb * 2 + 1][1] = r3;
            }
#pragma unroll
            for (int mi = 0; mi < 4; mi++)
#pragma unroll
                for (int ni = 0; ni < 4; ni++)
                    mma16816(acc[mi][ni], a[mi], b[ni]);
        }
    }

    // fused epilogue: hinge + indicator + triangular mask, reduce to scalar
    int g = lane >> 2, t4 = lane & 3;
    bool diag = (ti == tj);
    float lsum = 0.f;
#pragma unroll
    for (int mi = 0; mi < 4; mi++) {
#pragma unroll
        for (int ni = 0; ni < 4; ni++) {
#pragma unroll
            for (int e = 0; e < 4; e++) {
                int m = warp_m * 64 + mi * 16 + g + ((e >> 1) << 3);
                int n = warp_n * 32 + ni * 8 + t4 * 2 + (e & 1);
                if (!diag || n >= m) {
                    float h = 2.0f * acc[mi][ni][e] - (2.0f - THETA_F);
                    if (h > 0.f) lsum += (ysi[m] == ysj[n]) ? h : -h;
                }
            }
        }
    }
#pragma unroll
    for (int o = 16; o; o >>= 1) lsum += __shfl_xor_sync(0xffffffffu, lsum, o);
    if (lane == 0) wsum[wid] = lsum;
    __syncthreads();
    if (tid == 0) {
        float s = 0.f;
#pragma unroll
        for (int w = 0; w < 8; w++) s += wsum[w];
        atomicAdd(&g_total, (double)s);
    }
}

// ---------------------------------------------------------------------------
__global__ void finalize_kernel(float* __restrict__ out, int B) {
    double cnt = (double)B * ((double)B + 1.0) * 0.5;  // pairs with j >= i
    double total = XI_D * cnt + g_total;
    out[0] = (float)(total / ((double)B * (double)B - (double)B));
}

// ---------------------------------------------------------------------------
extern "C" void kernel_launch(void* const* d_in, const int* in_sizes, int n_in,
                              void* d_out, int out_size) {
    const float* x = (const float*)d_in[0];
    const void* y = d_in[1];
    int B = in_sizes[1];
    int D = in_sizes[0] / B;

    zero_kernel<<<1, 1>>>();
    detect_kernel<<<(B / 2 + 255) / 256, 256>>>((const unsigned*)y, B);
    normalize_kernel<<<B / 8, 256>>>(x, B, D);

    int NT = B / 128;
    int T = NT * (NT + 1) / 2;
    gemm_kernel<<<T, 256>>>(y, B, D, NT);

    finalize_kernel<<<1, 1>>>((float*)d_out, B);
}